// round 16
// baseline (speedup 1.0000x reference)
#include <cuda_runtime.h>

#define HD     64
#define VOC    64
#define HALF   32
#define BATCH  128
#define SEQLEN 2048

// ---- scratch tables (device globals; no allocation allowed) ----
__device__ __align__(16) float g_ks[VOC * HALF];
__device__ __align__(16) float g_ke[VOC * HALF];
__device__ __align__(16) float g_inv_s[VOC];
__device__ __align__(16) float g_inv_e[VOC];
__device__ __align__(16) float g_Ds[VOC * VOC];   // D[v1][v2] = ks(v1).ks(v2)
__device__ __align__(16) float g_De[VOC * VOC];   // D[v1][v2] = ke(v1).ke(v2)

typedef unsigned long long u64;

// fused per-(mem, v, lane) table: ((D[v][2l], D[v][2l+1]), (k[v][l], inv[v]))
__device__ __align__(16) ulonglong2 g_T[2 * VOC * HALF];

__device__ __forceinline__ u64 ffma2(u64 a, u64 b, u64 c) {
    u64 d;
    asm("fma.rn.f32x2 %0, %1, %2, %3;" : "=l"(d) : "l"(a), "l"(b), "l"(c));
    return d;
}
__device__ __forceinline__ u64 mul2(u64 a, u64 b) {
    u64 d;
    asm("mul.rn.f32x2 %0, %1, %2;" : "=l"(d) : "l"(a), "l"(b));
    return d;
}
__device__ __forceinline__ u64 add2(u64 a, u64 b) {
    u64 d;
    asm("add.rn.f32x2 %0, %1, %2;" : "=l"(d) : "l"(a), "l"(b));
    return d;
}
__device__ __forceinline__ u64 pack2(float x, float y) {
    u64 r;
    asm("mov.b64 %0, {%1, %2};" : "=l"(r) : "f"(x), "f"(y));
    return r;
}
__device__ __forceinline__ float2 unpack2(u64 v) {
    float x, y;
    asm("mov.b64 {%0, %1}, %2;" : "=f"(x), "=f"(y) : "l"(v));
    return make_float2(x, y);
}

// ============================================================================
// Kernel A: per-vocab-id table precompute (h depends only on token id).
// (R14 version — the R15 smem staging serialized loads and regressed.)
// ============================================================================
__global__ void precompute_kernel(
    const float* __restrict__ embed,
    const float* __restrict__ W1, const float* __restrict__ b1,
    const float* __restrict__ W2, const float* __restrict__ b2,
    const float* __restrict__ ln_g, const float* __restrict__ ln_b,
    const float* __restrict__ Ws, const float* __restrict__ bs,
    const float* __restrict__ We, const float* __restrict__ be)
{
    const int v = blockIdx.x;
    const int t = threadIdx.x;

    __shared__ float s_e[HD];
    __shared__ float s_a[2 * HD];
    __shared__ float s_x[HD];
    __shared__ float s_h[HD];
    __shared__ float s_kv[2 * HALF];

    if (t < HD) s_e[t] = embed[v * HD + t];
    __syncthreads();

    {   // hidden = relu(e @ W1 + b1), 128 units, one per thread
        float acc = b1[t];
        #pragma unroll
        for (int d = 0; d < HD; d++)
            acc = fmaf(s_e[d], W1[d * (2 * HD) + t], acc);
        s_a[t] = fmaxf(acc, 0.0f);
    }
    __syncthreads();

    if (t < HD) {   // ff = hidden @ W2 + b2 ; x = e + ff
        float f = b2[t];
        #pragma unroll
        for (int k = 0; k < 2 * HD; k++)
            f = fmaf(s_a[k], W2[k * HD + t], f);
        s_x[t] = s_e[t] + f;
    }
    __syncthreads();

    if (t < HD) {   // LayerNorm (redundant per thread — tiny)
        float mu = 0.0f;
        #pragma unroll
        for (int d = 0; d < HD; d++) mu += s_x[d];
        mu *= (1.0f / HD);
        float var = 0.0f;
        #pragma unroll
        for (int d = 0; d < HD; d++) {
            float dd = s_x[d] - mu;
            var = fmaf(dd, dd, var);
        }
        var *= (1.0f / HD);
        float r = 1.0f / sqrtf(var + 1e-5f);
        s_h[t] = fmaf((s_x[t] - mu) * r, ln_g[t], ln_b[t]);
    }
    __syncthreads();

    if (t < HALF) {             // k_sem = h @ Ws + bs
        float k = bs[t];
        #pragma unroll
        for (int d = 0; d < HD; d++)
            k = fmaf(s_h[d], Ws[d * HALF + t], k);
        g_ks[v * HALF + t] = k;
        s_kv[t] = k;
    } else if (t < 2 * HALF) {  // k_epi = h @ We + be
        const int j = t - HALF;
        float k = be[j];
        #pragma unroll
        for (int d = 0; d < HD; d++)
            k = fmaf(s_h[d], We[d * HALF + j], k);
        g_ke[v * HALF + j] = k;
        s_kv[t] = k;
    }
    __syncthreads();

    if (t == 0) {               // 1/(k.k + 1e-6)
        float den = 1e-6f;
        #pragma unroll
        for (int j = 0; j < HALF; j++) den = fmaf(s_kv[j], s_kv[j], den);
        g_inv_s[v] = 1.0f / den;
    } else if (t == 1) {
        float den = 1e-6f;
        #pragma unroll
        for (int j = 0; j < HALF; j++) den = fmaf(s_kv[HALF + j], s_kv[HALF + j], den);
        g_inv_e[v] = 1.0f / den;
    }
}

// ============================================================================
// Kernel A2: token-pair dot tables + the packed T table the scan consumes:
//   T[m][v][l] = ((D[v][2l], D[v][2l+1]), (k_m[v][l], inv_m[v]))
// ============================================================================
__global__ void dots_kernel()
{
    const int v1  = blockIdx.x;
    const int tid = threadIdx.x;
    const int v2  = tid & 63;
    const int mem = tid >> 6;

    __shared__ float s_drow[2][VOC];

    const float* tab = mem ? g_ke : g_ks;
    float d = 0.0f;
    #pragma unroll
    for (int j = 0; j < HALF; j++)
        d = fmaf(tab[v1 * HALF + j], tab[v2 * HALF + j], d);
    (mem ? g_De : g_Ds)[v1 * VOC + v2] = d;
    s_drow[mem][v2] = d;
    __syncthreads();

    const int l = tid & 63;
    if (l < HALF) {
        const float kl = (mem ? g_ke : g_ks)[v1 * HALF + l];
        const float iv = (mem ? g_inv_e : g_inv_s)[v1];
        ulonglong2 e;
        e.x = pack2(s_drow[mem][2 * l], s_drow[mem][2 * l + 1]);
        e.y = pack2(kl, iv);
        g_T[mem * (VOC * HALF) + v1 * HALF + l] = e;
    }
}

// ============================================================================
// Kernel B: backward adjoint scan, TOKEN-QUAD steps.
// Homogeneous recursion (query folded into S' init):
//   d_t = -S'_{t+1}[v_t],  dd_t = wiv_t d_t,  S'_t = S'_{t+1} + dd_t D[v_t,:]
//   S'_2048 = -Dq,  ctx = sum_t wkl_t d_t.
// Quad (a,b,c,d) = tokens (t, t-1, t-2, t-3): all four next-quad S lookups
// are shfl'd AFTER this quad's axpy (exact post-update -> no cross-quad
// corrections); in-quad coupling via 6 triangular D entries:
//   e_b = Rb + dd_a Dab;  e_c = Rc + dd_a Dac + dd_b Dbc;  e_d = ... (3 terms)
// The SEL+SHFL+chain latency cycle is amortized over 4 tokens; the axpy uses
// packed FFMA2 on a u64 S (4 ops, not 8). Signs folded into negated
// premultiplied weights (nwkl, nwiv).
//
// 256 threads: warp 0 = sem, warp 1 = epi; warps 2-7 preamble-only (exit).
// ============================================================================
__global__ void __launch_bounds__(256, 1) scan_kernel(
    const int* __restrict__ seq,
    const float* __restrict__ Wo,
    const float* __restrict__ bo,
    float* __restrict__ out)
{
    extern __shared__ int smem_raw[];
    int*        s_tokp = smem_raw;                         // 16 pad + 2048
    int*        s_tok  = s_tokp + 16;
    float*      s_D    = (float*)(s_tok + SEQLEN);         // 2 * 4096
    ulonglong2* s_T    = (ulonglong2*)(s_D + 2 * VOC * VOC); // 2*64*32 entries
    float*      s_ctx  = (float*)(s_T + 2 * VOC * HALF);   // 64

    const int b    = blockIdx.x;
    const int tid  = threadIdx.x;
    const int wid  = tid >> 5;
    const int mem  = wid & 1;                 // valid for wid 0,1
    const int lane = tid & 31;

    // ---- preamble: pure wide copies (8 warps cooperate) ----
    {
        const int4* seq4 = (const int4*)(seq + b * SEQLEN);
        int4* tok4 = (int4*)s_tok;
        #pragma unroll
        for (int i = tid; i < SEQLEN / 4; i += 256)
            tok4[i] = seq4[i];
        if (tid < 16) s_tokp[tid] = 0;        // pad: v = 0 (dead prefetch)

        float4* D4 = (float4*)s_D;
        const float4* gDs4 = (const float4*)g_Ds;
        const float4* gDe4 = (const float4*)g_De;
        #pragma unroll
        for (int i = tid; i < VOC * VOC / 4; i += 256) {
            D4[i]                 = gDs4[i];
            D4[VOC * VOC / 4 + i] = gDe4[i];
        }
        #pragma unroll
        for (int i = tid; i < 2 * VOC * HALF; i += 256)
            s_T[i] = g_T[i];
    }
    __syncthreads();

    if (wid >= 2) return;   // preamble helpers done (exited threads satisfy bar)

    const char* Db = (const char*)(s_D + mem * (VOC * VOC)); // + v*256 + v2*4
    const char* Tb = (const char*)(s_T + mem * (VOC * HALF)) + lane * 16; // + v*512

    // ---- prologue ----
    const int vq = s_tok[2047];               // query token id (= quad-0 a)
    const int vb0 = s_tok[2046];
    const int vc0 = s_tok[2045];
    const int vd0 = s_tok[2044];
    int o1a = s_tok[2043], o1b = s_tok[2042], o1c = s_tok[2041], o1d = s_tok[2040];
    int o2a = s_tok[2039], o2b = s_tok[2038], o2c = s_tok[2037], o2d = s_tok[2036];

    // S' init: S'_2048[v] = -D[v][vq]  (2 entries per lane, packed)
    const char* Dqcol = Db + vq * 4;
    u64 S2 = pack2(-*(const float*)(Dqcol + (2 * lane) * 256),
                   -*(const float*)(Dqcol + (2 * lane + 1) * 256));

    // quad 0 = (2047 dummy, 2046, 2045, 2044)
    float Ra = 0.0f;
    float Rb = -*(const float*)(Dqcol + vb0 * 256);
    float Rc = -*(const float*)(Dqcol + vc0 * 256);
    float Rd = -*(const float*)(Dqcol + vd0 * 256);

    float Dab = *(const float*)(Db + vq  * 256 + vb0 * 4);
    float Dac = *(const float*)(Db + vq  * 256 + vc0 * 4);
    float Dad = *(const float*)(Db + vq  * 256 + vd0 * 4);
    float Dbc = *(const float*)(Db + vb0 * 256 + vc0 * 4);
    float Dbd = *(const float*)(Db + vb0 * 256 + vd0 * 4);
    float Dcd = *(const float*)(Db + vc0 * 256 + vd0 * 4);

    const ulonglong2 TA0 = *(const ulonglong2*)(Tb + vq  * 512);
    const ulonglong2 TB0 = *(const ulonglong2*)(Tb + vb0 * 512);
    const ulonglong2 TC0 = *(const ulonglong2*)(Tb + vc0 * 512);
    const ulonglong2 TD0 = *(const ulonglong2*)(Tb + vd0 * 512);
    u64 DrA2 = TA0.x, DrB2 = TB0.x, DrC2 = TC0.x, DrD2 = TD0.x;

    const float wB0 = mem ? (2047.0f / 2048.0f) : 1.0f;
    const float wC0 = mem ? (2046.0f / 2048.0f) : 1.0f;
    const float wD0 = mem ? (2045.0f / 2048.0f) : 1.0f;
    float nwklA = 0.0f, nwivA = 0.0f;          // token 2047: dummy weight 0
    const float2 TB0hi = unpack2(TB0.y);
    const float2 TC0hi = unpack2(TC0.y);
    const float2 TD0hi = unpack2(TD0.y);
    float nwklB = -TB0hi.x * wB0, nwivB = -TB0hi.y * wB0;
    float nwklC = -TC0hi.x * wC0, nwivC = -TC0hi.y * wC0;
    float nwklD = -TD0hi.x * wD0, nwivD = -TD0hi.y * wD0;

    // counters: NEGATED weights for quad 1 tokens (2043..2040)
    u64 nwAp, nwBp, nwCp, nwDp, incp;
    if (mem) {
        nwAp = pack2(-2044.0f / 2048.0f, -2044.0f / 2048.0f);
        nwBp = pack2(-2043.0f / 2048.0f, -2043.0f / 2048.0f);
        nwCp = pack2(-2042.0f / 2048.0f, -2042.0f / 2048.0f);
        nwDp = pack2(-2041.0f / 2048.0f, -2041.0f / 2048.0f);
        incp = pack2(4.0f / 2048.0f, 4.0f / 2048.0f);
    } else {
        nwAp = pack2(-1.0f, -1.0f);
        nwBp = nwAp; nwCp = nwAp; nwDp = nwAp;
        incp = 0ull;
    }

    // quad-1 T entries (premul at iter 0 consumes these)
    ulonglong2 T1a = *(const ulonglong2*)(Tb + o1a * 512);
    ulonglong2 T1b = *(const ulonglong2*)(Tb + o1b * 512);
    ulonglong2 T1c = *(const ulonglong2*)(Tb + o1c * 512);
    ulonglong2 T1d = *(const ulonglong2*)(Tb + o1d * 512);

    int4 Q  = *(const int4*)(s_tok + 2032);   // quad-3 tokens [2032..2035]
    int4 Qn = Q;
    const int* qptr = s_tok + 2028;           // next refill

    float ctx = 0.0f;

#define QSTEP(LAST) do {                                                     \
    /* (1) current quad math (signs folded into negated premuls) */          \
    const float dd_a = nwivA * Ra;                                           \
    ctx = fmaf(Ra, nwklA, ctx);                                              \
    const float e_b = fmaf(dd_a, Dab, Rb);                                   \
    const float dd_b = nwivB * e_b;                                          \
    ctx = fmaf(e_b, nwklB, ctx);                                             \
    float e_c = fmaf(dd_a, Dac, Rc);                                         \
    e_c = fmaf(dd_b, Dbc, e_c);                                              \
    const float dd_c = nwivC * e_c;                                          \
    ctx = fmaf(e_c, nwklC, ctx);                                             \
    float e_d = fmaf(dd_a, Dad, Rd);                                         \
    e_d = fmaf(dd_b, Dbd, e_d);                                              \
    e_d = fmaf(dd_c, Dcd, e_d);                                              \
    const float dd_d = nwivD * e_d;                                          \
    ctx = fmaf(e_d, nwklD, ctx);                                             \
    /* (2) packed axpy: S' += sum dd_i Drow_i */                             \
    S2 = ffma2(pack2(dd_a, dd_a), DrA2, S2);                                 \
    S2 = ffma2(pack2(dd_b, dd_b), DrB2, S2);                                 \
    S2 = ffma2(pack2(dd_c, dd_c), DrC2, S2);                                 \
    S2 = ffma2(pack2(dd_d, dd_d), DrD2, S2);                                 \
    if (!(LAST)) {                                                           \
    const float2 su = unpack2(S2);                                           \
    /* (3) shfl lookups for NEXT quad (exact post-axpy reads) */             \
    const float sa = (o1a & 1) ? su.y : su.x;                                \
    const float sb = (o1b & 1) ? su.y : su.x;                                \
    const float sc = (o1c & 1) ? su.y : su.x;                                \
    const float sd = (o1d & 1) ? su.y : su.x;                                \
    const float Ra_n = __shfl_sync(0xffffffffu, sa, o1a >> 1);               \
    const float Rb_n = __shfl_sync(0xffffffffu, sb, o1b >> 1);               \
    const float Rc_n = __shfl_sync(0xffffffffu, sc, o1c >> 1);               \
    const float Rd_n = __shfl_sync(0xffffffffu, sd, o1d >> 1);               \
    Qn = *(const int4*)qptr; qptr -= 4;                                      \
    /* (4) T prefetch for quad+2 (addresses 1 iter old) */                   \
    const ulonglong2 Ta_n = *(const ulonglong2*)(Tb + o2a * 512);            \
    const ulonglong2 Tb_n = *(const ulonglong2*)(Tb + o2b * 512);            \
    const ulonglong2 Tc_n = *(const ulonglong2*)(Tb + o2c * 512);            \
    const ulonglong2 Td_n = *(const ulonglong2*)(Tb + o2d * 512);            \
    /* (5) triangular D entries for next quad */                             \
    const char* r1a_ = Db + o1a * 256;                                       \
    const char* r1b_ = Db + o1b * 256;                                       \
    const float Dab_n = *(const float*)(r1a_ + o1b * 4);                     \
    const float Dac_n = *(const float*)(r1a_ + o1c * 4);                     \
    const float Dad_n = *(const float*)(r1a_ + o1d * 4);                     \
    const float Dbc_n = *(const float*)(r1b_ + o1c * 4);                     \
    const float Dbd_n = *(const float*)(r1b_ + o1d * 4);                     \
    const float Dcd_n = *(const float*)(Db + o1c * 256 + o1d * 4);           \
    /* (6) premuls for next quad from last iter's T loads */                 \
    const u64 wpa = mul2(T1a.y, nwAp);                                       \
    const u64 wpb = mul2(T1b.y, nwBp);                                       \
    const u64 wpc = mul2(T1c.y, nwCp);                                       \
    const u64 wpd = mul2(T1d.y, nwDp);                                       \
    nwAp = add2(nwAp, incp); nwBp = add2(nwBp, incp);                        \
    nwCp = add2(nwCp, incp); nwDp = add2(nwDp, incp);                        \
    const float2 wau = unpack2(wpa);                                         \
    const float2 wbu = unpack2(wpb);                                         \
    const float2 wcu = unpack2(wpc);                                         \
    const float2 wdu = unpack2(wpd);                                         \
    /* (7) rotate */                                                         \
    Ra = Ra_n; Rb = Rb_n; Rc = Rc_n; Rd = Rd_n;                              \
    Dab = Dab_n; Dac = Dac_n; Dad = Dad_n;                                   \
    Dbc = Dbc_n; Dbd = Dbd_n; Dcd = Dcd_n;                                   \
    nwklA = wau.x; nwivA = wau.y;                                            \
    nwklB = wbu.x; nwivB = wbu.y;                                            \
    nwklC = wcu.x; nwivC = wcu.y;                                            \
    nwklD = wdu.x; nwivD = wdu.y;                                            \
    DrA2 = T1a.x; DrB2 = T1b.x; DrC2 = T1c.x; DrD2 = T1d.x;                  \
    T1a = Ta_n; T1b = Tb_n; T1c = Tc_n; T1d = Td_n;                          \
    o1a = o2a; o1b = o2b; o1c = o2c; o1d = o2d;                              \
    o2a = Q.w; o2b = Q.z; o2c = Q.y; o2d = Q.x;                              \
    Q = Qn;                                                                  \
    }                                                                        \
} while (0)

    for (int it = 0; it < 511; it++)
        QSTEP(0);
    QSTEP(1);     // last quad: skip lookahead machinery
#undef QSTEP

    s_ctx[mem * HALF + lane] = ctx;
    __syncthreads();

    // out[b] = [ctx_s, ctx_e] @ Wo + bo   (64 threads, one column each)
    {
        float o = bo[tid];
        #pragma unroll
        for (int i = 0; i < 2 * HALF; i++)
            o = fmaf(s_ctx[i], Wo[i * VOC + tid], o);
        out[b * VOC + tid] = o;
    }
}

// ============================================================================
// Launch. Inputs in metadata order:
// 0:seq 1:embed 2:W1 3:b1 4:W2 5:b2 6:ln_g 7:ln_b 8:Ws 9:bs 10:We 11:be 12:Wo 13:bo
// ============================================================================
// Byte-accurate layout:
//   tok pad+ring: (16 + SEQLEN) * 4 =  8256
//   s_D:          2*VOC*VOC * 4     = 32768
//   s_T:          2*VOC*HALF * 16   = 65536
//   s_ctx:        VOC * 4           =   256
#define SCAN_SMEM_BYTES ((16 + SEQLEN) * 4 + 2*VOC*VOC*4 + 2*VOC*HALF*16 + VOC*4)

extern "C" void kernel_launch(void* const* d_in, const int* in_sizes, int n_in,
                              void* d_out, int out_size)
{
    const int*   seq   = (const int*)  d_in[0];
    const float* embed = (const float*)d_in[1];
    const float* W1    = (const float*)d_in[2];
    const float* b1    = (const float*)d_in[3];
    const float* W2    = (const float*)d_in[4];
    const float* b2    = (const float*)d_in[5];
    const float* ln_g  = (const float*)d_in[6];
    const float* ln_b  = (const float*)d_in[7];
    const float* Ws    = (const float*)d_in[8];
    const float* bs    = (const float*)d_in[9];
    const float* We    = (const float*)d_in[10];
    const float* be    = (const float*)d_in[11];
    const float* Wo    = (const float*)d_in[12];
    const float* bo    = (const float*)d_in[13];

    cudaFuncSetAttribute(scan_kernel,
                         cudaFuncAttributeMaxDynamicSharedMemorySize,
                         SCAN_SMEM_BYTES);

    precompute_kernel<<<VOC, 128>>>(embed, W1, b1, W2, b2, ln_g, ln_b,
                                    Ws, bs, We, be);
    dots_kernel<<<VOC, 128>>>();
    scan_kernel<<<BATCH, 256, SCAN_SMEM_BYTES>>>(seq, Wo, bo, (float*)d_out);
}

// round 17
// speedup vs baseline: 1.1220x; 1.1220x over previous
#include <cuda_runtime.h>

#define HD     64
#define VOC    64
#define HALF   32
#define BATCH  128
#define SEQLEN 2048

// ---- scratch tables (device globals; no allocation allowed) ----
__device__ __align__(16) float g_ks[VOC * HALF];
__device__ __align__(16) float g_ke[VOC * HALF];
__device__ __align__(16) float g_inv_s[VOC];
__device__ __align__(16) float g_inv_e[VOC];
__device__ __align__(16) float g_Ds[VOC * VOC];   // D[v1][v2] = ks(v1).ks(v2)
__device__ __align__(16) float g_De[VOC * VOC];   // D[v1][v2] = ke(v1).ke(v2)

typedef unsigned long long u64;

// fused per-(mem, v, lane) table: ((D[v][2l], D[v][2l+1]), (k[v][l], inv[v]))
__device__ __align__(16) ulonglong2 g_T[2 * VOC * HALF];

__device__ __forceinline__ u64 mul2(u64 a, u64 b) {
    u64 d;
    asm("mul.rn.f32x2 %0, %1, %2;" : "=l"(d) : "l"(a), "l"(b));
    return d;
}
__device__ __forceinline__ u64 add2(u64 a, u64 b) {
    u64 d;
    asm("add.rn.f32x2 %0, %1, %2;" : "=l"(d) : "l"(a), "l"(b));
    return d;
}
__device__ __forceinline__ u64 pack2(float x, float y) {
    u64 r;
    asm("mov.b64 %0, {%1, %2};" : "=l"(r) : "f"(x), "f"(y));
    return r;
}
__device__ __forceinline__ float2 unpack2(u64 v) {
    float x, y;
    asm("mov.b64 {%0, %1}, %2;" : "=f"(x), "=f"(y) : "l"(v));
    return make_float2(x, y);
}

// ============================================================================
// Kernel A: per-vocab-id table precompute (h depends only on token id).
// v2: 256 threads with split-K on every matmul loop — loads per thread drop
// 192 -> 80 and warps/SM double, attacking the L2-latency serialization that
// made v1 take 9.3 us. Partial sums combine via shfl_xor within warps.
// ============================================================================
__global__ void __launch_bounds__(256, 1) precompute_kernel(
    const float* __restrict__ embed,
    const float* __restrict__ W1, const float* __restrict__ b1,
    const float* __restrict__ W2, const float* __restrict__ b2,
    const float* __restrict__ ln_g, const float* __restrict__ ln_b,
    const float* __restrict__ Ws, const float* __restrict__ bs,
    const float* __restrict__ We, const float* __restrict__ be)
{
    const int v = blockIdx.x;
    const int t = threadIdx.x;

    __shared__ float s_e[HD];
    __shared__ float s_a[2 * HD];
    __shared__ float s_x[HD];
    __shared__ float s_h[HD];
    __shared__ float s_kv[2 * HALF];

    if (t < HD) s_e[t] = embed[v * HD + t];
    __syncthreads();

    {   // hidden = relu(e @ W1 + b1): unit u = t>>1, half h = t&1 (32 d each)
        const int u = t >> 1;
        const int h = t & 1;
        float acc = h ? 0.0f : b1[u];
        const int d0 = h * 32;
        #pragma unroll
        for (int d = 0; d < 32; d++)
            acc = fmaf(s_e[d0 + d], W1[(d0 + d) * (2 * HD) + u], acc);
        acc += __shfl_xor_sync(0xffffffffu, acc, 1);
        if (h == 0) s_a[u] = fmaxf(acc, 0.0f);
    }
    __syncthreads();

    {   // ff = hidden @ W2 + b2 ; x = e + ff: output o = t>>2, quarter q = t&3
        const int o = t >> 2;
        const int q = t & 3;
        float acc = (q == 0) ? b2[o] : 0.0f;
        const int k0 = q * 32;
        #pragma unroll
        for (int k = 0; k < 32; k++)
            acc = fmaf(s_a[k0 + k], W2[(k0 + k) * HD + o], acc);
        acc += __shfl_xor_sync(0xffffffffu, acc, 1);
        acc += __shfl_xor_sync(0xffffffffu, acc, 2);
        if (q == 0) s_x[o] = s_e[o] + acc;
    }
    __syncthreads();

    if (t < HD) {   // LayerNorm (redundant per thread — tiny)
        float mu = 0.0f;
        #pragma unroll
        for (int d = 0; d < HD; d++) mu += s_x[d];
        mu *= (1.0f / HD);
        float var = 0.0f;
        #pragma unroll
        for (int d = 0; d < HD; d++) {
            float dd = s_x[d] - mu;
            var = fmaf(dd, dd, var);
        }
        var *= (1.0f / HD);
        float r = 1.0f / sqrtf(var + 1e-5f);
        s_h[t] = fmaf((s_x[t] - mu) * r, ln_g[t], ln_b[t]);
    }
    __syncthreads();

    {   // k_sem / k_epi: 64 outputs (32 sem + 32 epi), 4 threads each (16 d)
        const int j = t >> 2;        // 0..63
        const int q = t & 3;
        const int col = j & 31;
        const float* W = (j < HALF) ? Ws : We;
        const float* bb = (j < HALF) ? bs : be;
        float acc = (q == 0) ? bb[col] : 0.0f;
        const int d0 = q * 16;
        #pragma unroll
        for (int d = 0; d < 16; d++)
            acc = fmaf(s_h[d0 + d], W[(d0 + d) * HALF + col], acc);
        acc += __shfl_xor_sync(0xffffffffu, acc, 1);
        acc += __shfl_xor_sync(0xffffffffu, acc, 2);
        if (q == 0) {
            if (j < HALF) g_ks[v * HALF + col] = acc;
            else          g_ke[v * HALF + col] = acc;
            s_kv[j] = acc;
        }
    }
    __syncthreads();

    if (t == 0) {               // 1/(k.k + 1e-6)
        float den = 1e-6f;
        #pragma unroll
        for (int j = 0; j < HALF; j++) den = fmaf(s_kv[j], s_kv[j], den);
        g_inv_s[v] = 1.0f / den;
    } else if (t == 1) {
        float den = 1e-6f;
        #pragma unroll
        for (int j = 0; j < HALF; j++) den = fmaf(s_kv[HALF + j], s_kv[HALF + j], den);
        g_inv_e[v] = 1.0f / den;
    }
}

// ============================================================================
// Kernel A2: token-pair dot tables + the packed T table the scan consumes:
//   T[m][v][l] = ((D[v][2l], D[v][2l+1]), (k_m[v][l], inv_m[v]))
// ============================================================================
__global__ void dots_kernel()
{
    const int v1  = blockIdx.x;
    const int tid = threadIdx.x;
    const int v2  = tid & 63;
    const int mem = tid >> 6;

    __shared__ float s_drow[2][VOC];

    const float* tab = mem ? g_ke : g_ks;
    float d = 0.0f;
    #pragma unroll
    for (int j = 0; j < HALF; j++)
        d = fmaf(tab[v1 * HALF + j], tab[v2 * HALF + j], d);
    (mem ? g_De : g_Ds)[v1 * VOC + v2] = d;
    s_drow[mem][v2] = d;
    __syncthreads();

    const int l = tid & 63;
    if (l < HALF) {
        const float kl = (mem ? g_ke : g_ks)[v1 * HALF + l];
        const float iv = (mem ? g_inv_e : g_inv_s)[v1];
        ulonglong2 e;
        e.x = pack2(s_drow[mem][2 * l], s_drow[mem][2 * l + 1]);
        e.y = pack2(kl, iv);
        g_T[mem * (VOC * HALF) + v1 * HALF + l] = e;
    }
}

// ============================================================================
// Kernel B: backward adjoint scan, TOKEN-PAIR steps. (Exact R14 structure —
// the measured optimum; R16's quad blocking regressed.)
// Homogeneous recursion (query folded into S' init):
//   d_t = -S'_{t+1}[v_t],  dd_t = wiv_t d_t,  S'_t = S'_{t+1} + dd_t D[v_t,:]
//   S'_2048 = -Dq,  ctx = sum_t wkl_t d_t.
// Pair (a,b) = (t, t-1): both next-pair S lookups are shfl'd AFTER this
// pair's axpy (exact post-update reads -> NO cross-pair corrections); the
// only in-pair coupling is e_b = fma(dd_a, D[v_a,v_b], Rb).
// Signs folded into negated premultiplied weights (nwkl, nwiv).
//
// 256 threads: warp 0 = sem, warp 1 = epi; warps 2-7 preamble-only (exit).
// ============================================================================
__global__ void __launch_bounds__(256, 1) scan_kernel(
    const int* __restrict__ seq,
    const float* __restrict__ Wo,
    const float* __restrict__ bo,
    float* __restrict__ out)
{
    extern __shared__ int smem_raw[];
    int*        s_tokp = smem_raw;                         // 16 pad + 2048
    int*        s_tok  = s_tokp + 16;
    float*      s_D    = (float*)(s_tok + SEQLEN);         // 2 * 4096
    ulonglong2* s_T    = (ulonglong2*)(s_D + 2 * VOC * VOC); // 2*64*32 entries
    float*      s_ctx  = (float*)(s_T + 2 * VOC * HALF);   // 64

    const int b    = blockIdx.x;
    const int tid  = threadIdx.x;
    const int wid  = tid >> 5;
    const int mem  = wid & 1;                 // valid for wid 0,1
    const int lane = tid & 31;

    // ---- preamble: pure wide copies (8 warps cooperate) ----
    {
        const int4* seq4 = (const int4*)(seq + b * SEQLEN);
        int4* tok4 = (int4*)s_tok;
        #pragma unroll
        for (int i = tid; i < SEQLEN / 4; i += 256)
            tok4[i] = seq4[i];
        if (tid < 16) s_tokp[tid] = 0;        // pad: v = 0 (dead prefetch)

        float4* D4 = (float4*)s_D;
        const float4* gDs4 = (const float4*)g_Ds;
        const float4* gDe4 = (const float4*)g_De;
        #pragma unroll
        for (int i = tid; i < VOC * VOC / 4; i += 256) {
            D4[i]                 = gDs4[i];
            D4[VOC * VOC / 4 + i] = gDe4[i];
        }
        #pragma unroll
        for (int i = tid; i < 2 * VOC * HALF; i += 256)
            s_T[i] = g_T[i];
    }
    __syncthreads();

    if (wid >= 2) return;   // preamble helpers done (exited threads satisfy bar)

    const char* Db = (const char*)(s_D + mem * (VOC * VOC)); // + v*256 + v2*4
    const char* Tb = (const char*)(s_T + mem * (VOC * HALF)) + lane * 16; // + v*512

    // ---- prologue ----
    const int vq  = s_tok[2047];              // query token id (= pair-0 a)
    const int v46 = s_tok[2046];              // pair-0 b
    int o_a1 = s_tok[2045], o_b1 = s_tok[2044];   // pair 1
    int o_a2 = s_tok[2043], o_b2 = s_tok[2042];   // pair 2

    // S' init: S'_2048[v] = -D[v][vq]
    const char* Dqcol = Db + vq * 4;
    float Slo = -*(const float*)(Dqcol + (2 * lane) * 256);
    float Shi = -*(const float*)(Dqcol + (2 * lane + 1) * 256);

    // pair 0 = (2047 dummy, 2046)
    float Ra = 0.0f;                                          // unused (nwA=0)
    float Rb = -*(const float*)(Dqcol + v46 * 256);           // S'_2048[v46]
    float Dab = *(const float*)(Db + vq * 256 + v46 * 4);     // D[vq][v46]

    const ulonglong2 T47 = *(const ulonglong2*)(Tb + vq * 512);
    const ulonglong2 T46 = *(const ulonglong2*)(Tb + v46 * 512);
    float2 DrA = unpack2(T47.x);
    float2 DrB = unpack2(T46.x);

    const float wB0 = mem ? (2047.0f / 2048.0f) : 1.0f;
    float nwklA = 0.0f, nwivA = 0.0f;         // token 2047: dummy weight 0
    const float2 T46hi = unpack2(T46.y);
    float nwklB = -T46hi.x * wB0;
    float nwivB = -T46hi.y * wB0;

    // counters hold NEXT pair's negated weights (packed same value twice)
    u64 nwa2p, nwb2p, inc2p;
    if (mem) {
        nwa2p = pack2(-2046.0f / 2048.0f, -2046.0f / 2048.0f);
        nwb2p = pack2(-2045.0f / 2048.0f, -2045.0f / 2048.0f);
        inc2p = pack2(2.0f / 2048.0f, 2.0f / 2048.0f);
    } else {
        nwa2p = pack2(-1.0f, -1.0f);
        nwb2p = pack2(-1.0f, -1.0f);
        inc2p = 0ull;
    }

    ulonglong2 T_a1 = *(const ulonglong2*)(Tb + o_a1 * 512);  // pair-1 T
    ulonglong2 T_b1 = *(const ulonglong2*)(Tb + o_b1 * 512);

    int4 Q  = *(const int4*)(s_tok + 2040);   // tokens [2040..2043]
    int4 Qn = Q;
    const int* qptr = s_tok + 2036;           // next refill

    float ctx = 0.0f;

#define PSTEP(INSA, INSB, LOADQ) do {                                        \
    /* (1) current pair math (signs folded into negated premuls) */          \
    const float dd_a = nwivA * Ra;                                           \
    ctx = fmaf(Ra, nwklA, ctx);                                              \
    const float e_b = fmaf(dd_a, Dab, Rb);                                   \
    const float dd_b = nwivB * e_b;                                          \
    ctx = fmaf(e_b, nwklB, ctx);                                             \
    /* (2) axpy: S' += dd_a DrowA + dd_b DrowB */                            \
    Slo = fmaf(dd_a, DrA.x, Slo);                                            \
    Shi = fmaf(dd_a, DrA.y, Shi);                                            \
    Slo = fmaf(dd_b, DrB.x, Slo);                                            \
    Shi = fmaf(dd_b, DrB.y, Shi);                                            \
    /* (3) shfl lookups for NEXT pair (exact post-axpy reads) */             \
    const float sva = (o_a1 & 1) ? Shi : Slo;                                \
    const float svb = (o_b1 & 1) ? Shi : Slo;                                \
    const float Ra_n = __shfl_sync(0xffffffffu, sva, o_a1 >> 1);             \
    const float Rb_n = __shfl_sync(0xffffffffu, svb, o_b1 >> 1);             \
    if (LOADQ) { Qn = *(const int4*)qptr; qptr -= 4; }                       \
    /* (4) T prefetch for pair+2 (addresses 1 iter old) */                   \
    const ulonglong2 Ta_n = *(const ulonglong2*)(Tb + o_a2 * 512);           \
    const ulonglong2 Tb_n = *(const ulonglong2*)(Tb + o_b2 * 512);           \
    /* (5) in-pair D entry for next pair */                                  \
    const float Dab_n = *(const float*)(Db + o_a1 * 256 + o_b1 * 4);         \
    /* (6) premuls + Drows for next pair from last iter's T loads */         \
    const u64 wpa = mul2(T_a1.y, nwa2p);                                     \
    const u64 wpb = mul2(T_b1.y, nwb2p);                                     \
    nwa2p = add2(nwa2p, inc2p);                                              \
    nwb2p = add2(nwb2p, inc2p);                                              \
    const float2 wau = unpack2(wpa);                                         \
    const float2 wbu = unpack2(wpb);                                         \
    const float2 drA_n = unpack2(T_a1.x);                                    \
    const float2 drB_n = unpack2(T_b1.x);                                    \
    /* (7) rotate */                                                         \
    Ra = Ra_n; Rb = Rb_n; Dab = Dab_n;                                       \
    nwklA = wau.x; nwivA = wau.y;                                            \
    nwklB = wbu.x; nwivB = wbu.y;                                            \
    DrA = drA_n; DrB = drB_n;                                                \
    T_a1 = Ta_n; T_b1 = Tb_n;                                                \
    o_a1 = o_a2; o_b1 = o_b2;                                                \
    o_a2 = (INSA); o_b2 = (INSB);                                            \
} while (0)

    for (int it = 0; it < 1024; it += 2) {
        PSTEP(Q.y, Q.x, 1);      // even iter: inserts pair from Q.y/Q.x
        PSTEP(Qn.w, Qn.z, 0);    // odd iter
        Q = Qn;
    }
#undef PSTEP

    s_ctx[mem * HALF + lane] = ctx;
    __syncthreads();

    // out[b] = [ctx_s, ctx_e] @ Wo + bo   (64 threads, one column each)
    {
        float o = bo[tid];
        #pragma unroll
        for (int i = 0; i < 2 * HALF; i++)
            o = fmaf(s_ctx[i], Wo[i * VOC + tid], o);
        out[b * VOC + tid] = o;
    }
}

// ============================================================================
// Launch. Inputs in metadata order:
// 0:seq 1:embed 2:W1 3:b1 4:W2 5:b2 6:ln_g 7:ln_b 8:Ws 9:bs 10:We 11:be 12:Wo 13:bo
// ============================================================================
// Byte-accurate layout:
//   tok pad+ring: (16 + SEQLEN) * 4 =  8256
//   s_D:          2*VOC*VOC * 4     = 32768
//   s_T:          2*VOC*HALF * 16   = 65536
//   s_ctx:        VOC * 4           =   256
#define SCAN_SMEM_BYTES ((16 + SEQLEN) * 4 + 2*VOC*VOC*4 + 2*VOC*HALF*16 + VOC*4)

extern "C" void kernel_launch(void* const* d_in, const int* in_sizes, int n_in,
                              void* d_out, int out_size)
{
    const int*   seq   = (const int*)  d_in[0];
    const float* embed = (const float*)d_in[1];
    const float* W1    = (const float*)d_in[2];
    const float* b1    = (const float*)d_in[3];
    const float* W2    = (const float*)d_in[4];
    const float* b2    = (const float*)d_in[5];
    const float* ln_g  = (const float*)d_in[6];
    const float* ln_b  = (const float*)d_in[7];
    const float* Ws    = (const float*)d_in[8];
    const float* bs    = (const float*)d_in[9];
    const float* We    = (const float*)d_in[10];
    const float* be    = (const float*)d_in[11];
    const float* Wo    = (const float*)d_in[12];
    const float* bo    = (const float*)d_in[13];

    cudaFuncSetAttribute(scan_kernel,
                         cudaFuncAttributeMaxDynamicSharedMemorySize,
                         SCAN_SMEM_BYTES);

    precompute_kernel<<<VOC, 256>>>(embed, W1, b1, W2, b2, ln_g, ln_b,
                                    Ws, bs, We, be);
    dots_kernel<<<VOC, 128>>>();
    scan_kernel<<<BATCH, 256, SCAN_SMEM_BYTES>>>(seq, Wo, bo, (float*)d_out);
}